// round 1
// baseline (speedup 1.0000x reference)
#include <cuda_runtime.h>
#include <math.h>

// Problem dims (fixed by the dataset)
#define BATCH 2048
#define TT    20
#define CD    512
#define HD    1024
#define VD    2048
#define QD    1024

// ---------------- scratch (static device globals; no runtime allocation) ----
__device__ float g_fv  [BATCH * CD];
__device__ float g_fq  [BATCH * CD];
__device__ float g_fvq [BATCH * CD];
__device__ float g_gi1 [BATCH * TT * 3 * CD];   // hoisted input GEMM of GRU1, row = b*TT + t
__device__ float g_gh1 [BATCH * 3 * CD];
__device__ float g_att [BATCH * CD];
__device__ float g_gi2 [BATCH * 3 * HD];
__device__ float g_gh2 [BATCH * 3 * HD];
__device__ float g_h1  [BATCH * CD];
__device__ float g_h2  [BATCH * HD];
__device__ float g_h2a [BATCH * TT * HD];       // all h2_t, row = b*TT + t
__device__ float g_y   [BATCH * TT * HD];       // h2a @ Wfc^T

// ---------------- helpers ----------------------------------------------------
__device__ __forceinline__ float sigmf(float x) { return 1.0f / (1.0f + expf(-x)); }
__device__ __forceinline__ float leakyf(float x) { return x > 0.0f ? x : 0.01f * x; }

// ---------------- generic SGEMM: C[M,N] = A[M,K] @ B[N,K]^T (+bias) ----------
// 128x128 block tile, K-step 8, 256 threads, 8x8 per-thread microtile.
// All M,N divisible by 128; K divisible by 8 (true for every call here).
__global__ __launch_bounds__(256) void sgemm_nt(
    const float* __restrict__ A, const float* __restrict__ B,
    const float* __restrict__ bias, float* __restrict__ C,
    int M, int N, int K, int epi /*0=none,1=leaky*/)
{
    __shared__ float As[8][128];
    __shared__ float Bs[8][128];

    const int tid = threadIdx.x;
    const int bm = blockIdx.y * 128;
    const int bn = blockIdx.x * 128;

    const int lrow = tid >> 1;        // 0..127
    const int lcol = (tid & 1) << 2;  // 0 or 4

    const float* Ap = A + (size_t)(bm + lrow) * K + lcol;
    const float* Bp = B + (size_t)(bn + lrow) * K + lcol;

    const int tx = tid & 15;   // n-direction
    const int ty = tid >> 4;   // m-direction

    float acc[8][8];
#pragma unroll
    for (int i = 0; i < 8; i++)
#pragma unroll
        for (int j = 0; j < 8; j++) acc[i][j] = 0.0f;

    for (int k0 = 0; k0 < K; k0 += 8) {
        float4 a4 = *(const float4*)(Ap + k0);
        float4 b4 = *(const float4*)(Bp + k0);
        __syncthreads();
        As[lcol + 0][lrow] = a4.x; As[lcol + 1][lrow] = a4.y;
        As[lcol + 2][lrow] = a4.z; As[lcol + 3][lrow] = a4.w;
        Bs[lcol + 0][lrow] = b4.x; Bs[lcol + 1][lrow] = b4.y;
        Bs[lcol + 2][lrow] = b4.z; Bs[lcol + 3][lrow] = b4.w;
        __syncthreads();

#pragma unroll
        for (int k = 0; k < 8; k++) {
            float af[8], bf[8];
            *(float4*)&af[0] = *(const float4*)&As[k][ty * 8];
            *(float4*)&af[4] = *(const float4*)&As[k][ty * 8 + 4];
            *(float4*)&bf[0] = *(const float4*)&Bs[k][tx * 8];
            *(float4*)&bf[4] = *(const float4*)&Bs[k][tx * 8 + 4];
#pragma unroll
            for (int i = 0; i < 8; i++)
#pragma unroll
                for (int j = 0; j < 8; j++)
                    acc[i][j] = fmaf(af[i], bf[j], acc[i][j]);
        }
    }

    // epilogue
#pragma unroll
    for (int i = 0; i < 8; i++) {
        const int row = bm + ty * 8 + i;
        float out[8];
#pragma unroll
        for (int j = 0; j < 8; j++) {
            float v = acc[i][j];
            if (bias) v += bias[bn + tx * 8 + j];
            if (epi == 1) v = leakyf(v);
            out[j] = v;
        }
        float* Cp = C + (size_t)row * N + bn + tx * 8;
        *(float4*)(Cp)     = *(float4*)&out[0];
        *(float4*)(Cp + 4) = *(float4*)&out[4];
    }
}

// ---------------- elementwise kernels ----------------------------------------
__global__ void zero_kernel(float* p, int n) {
    int i = blockIdx.x * blockDim.x + threadIdx.x;
    if (i < n) p[i] = 0.0f;
}

__global__ void add_kernel(const float* __restrict__ a, const float* __restrict__ b,
                           float* __restrict__ c, int n) {
    int i = blockIdx.x * blockDim.x + threadIdx.x;
    if (i < n) c[i] = a[i] + b[i];
}

// GRU1 gate fusion + attention + alphas write. One thread per (b, j<CD).
__global__ void gru1_att_kernel(
    const float* __restrict__ gi1,      // [B*T, 3CD], row b*TT+t
    const float* __restrict__ gh1,      // [B, 3CD]
    const float* __restrict__ caption,  // [B, T, CD]
    const float* __restrict__ fvq,      // [B, CD]
    const int*   __restrict__ cap_len,  // [B]
    float* __restrict__ h1,             // [B, CD] in/out
    float* __restrict__ att,            // [B, CD]
    float* __restrict__ alphas,         // [B, T, CD] (region of d_out)
    int t)
{
    int idx = blockIdx.x * blockDim.x + threadIdx.x;
    if (idx >= BATCH * CD) return;
    int b = idx / CD, j = idx - b * CD;
    bool active = t < cap_len[b];

    const float* gi = gi1 + (size_t)(b * TT + t) * (3 * CD);
    const float* gh = gh1 + (size_t)b * (3 * CD);

    float hv = h1[idx];
    float r = sigmf(gi[j]          + gh[j]);
    float z = sigmf(gi[CD + j]     + gh[CD + j]);
    float n = tanhf(gi[2 * CD + j] + r * gh[2 * CD + j]);
    float hn = (1.0f - z) * n + z * hv;
    float h  = active ? hn : hv;
    h1[idx] = h;

    float x = caption[(size_t)(b * TT + t) * CD + j];
    float a = sigmf(h * fvq[idx]) * x;
    att[idx] = a;
    alphas[(size_t)(b * TT + t) * CD + j] = active ? a : 0.0f;
}

// GRU2 gate fusion; writes h2 and h2_all. One thread per (b, j<HD).
__global__ void gru2_kernel(
    const float* __restrict__ gi2,      // [B, 3HD]
    const float* __restrict__ gh2,      // [B, 3HD]
    const int*   __restrict__ cap_len,
    float* __restrict__ h2,             // [B, HD] in/out
    float* __restrict__ h2all,          // [B*T, HD], row b*TT+t
    int t)
{
    int idx = blockIdx.x * blockDim.x + threadIdx.x;
    if (idx >= BATCH * HD) return;
    int b = idx / HD, j = idx - b * HD;
    bool active = t < cap_len[b];

    const float* gi = gi2 + (size_t)b * (3 * HD);
    const float* gh = gh2 + (size_t)b * (3 * HD);

    float hv = h2[idx];
    float r = sigmf(gi[j]          + gh[j]);
    float z = sigmf(gi[HD + j]     + gh[HD + j]);
    float n = tanhf(gi[2 * HD + j] + r * gh[2 * HD + j]);
    float hn = (1.0f - z) * n + z * hv;
    float h  = active ? hn : hv;
    h2[idx] = h;
    h2all[(size_t)(b * TT + t) * HD + j] = h;
}

// Final reduction: out[b,j] = max_t ( t<len ? leaky(Y[b*TT+t, j]) : 0 )
__global__ void maxreduce_kernel(
    const float* __restrict__ Y,        // [B*T, HD]
    const int*   __restrict__ cap_len,
    float* __restrict__ out)            // [B, HD]
{
    int idx = blockIdx.x * blockDim.x + threadIdx.x;
    if (idx >= BATCH * HD) return;
    int b = idx / HD, j = idx - b * HD;
    int len = cap_len[b];
    float m = -INFINITY;
#pragma unroll
    for (int t = 0; t < TT; t++) {
        float v = (t < len) ? leakyf(Y[(size_t)(b * TT + t) * HD + j]) : 0.0f;
        m = fmaxf(m, v);
    }
    out[idx] = m;
}

// ---------------- launch ------------------------------------------------------
static inline dim3 gemm_grid(int M, int N) { return dim3(N / 128, M / 128); }

extern "C" void kernel_launch(void* const* d_in, const int* in_sizes, int n_in,
                              void* d_out, int out_size)
{
    // input order per setup_inputs()
    const float* v       = (const float*)d_in[0];
    const float* q       = (const float*)d_in[1];
    const float* caption = (const float*)d_in[2];
    const int*   cap_len = (const int*)  d_in[3];
    const float* w_ih1   = (const float*)d_in[4];
    const float* w_hh1   = (const float*)d_in[5];
    const float* b_ih1   = (const float*)d_in[6];
    const float* b_hh1   = (const float*)d_in[7];
    const float* w_ih2   = (const float*)d_in[8];
    const float* w_hh2   = (const float*)d_in[9];
    const float* b_ih2   = (const float*)d_in[10];
    const float* b_hh2   = (const float*)d_in[11];
    const float* Wv      = (const float*)d_in[12];
    const float* Wq      = (const float*)d_in[13];
    const float* Wfc     = (const float*)d_in[14];

    float* out    = (float*)d_out;                 // [B, HD]
    float* alphas = (float*)d_out + (size_t)BATCH * HD;  // [B, T, CD]

    float *fv, *fq, *fvq, *gi1, *gh1, *att, *gi2, *gh2, *h1, *h2, *h2a, *y;
    cudaGetSymbolAddress((void**)&fv,  g_fv);
    cudaGetSymbolAddress((void**)&fq,  g_fq);
    cudaGetSymbolAddress((void**)&fvq, g_fvq);
    cudaGetSymbolAddress((void**)&gi1, g_gi1);
    cudaGetSymbolAddress((void**)&gh1, g_gh1);
    cudaGetSymbolAddress((void**)&att, g_att);
    cudaGetSymbolAddress((void**)&gi2, g_gi2);
    cudaGetSymbolAddress((void**)&gh2, g_gh2);
    cudaGetSymbolAddress((void**)&h1,  g_h1);
    cudaGetSymbolAddress((void**)&h2,  g_h2);
    cudaGetSymbolAddress((void**)&h2a, g_h2a);
    cudaGetSymbolAddress((void**)&y,   g_y);

    const int EW = 256;

    // init recurrent state
    zero_kernel<<<(BATCH * CD + EW - 1) / EW, EW>>>(h1, BATCH * CD);
    zero_kernel<<<(BATCH * HD + EW - 1) / EW, EW>>>(h2, BATCH * HD);

    // hoisted projections
    sgemm_nt<<<gemm_grid(BATCH, CD), 256>>>(v, Wv, nullptr, fv, BATCH, CD, VD, 1);
    sgemm_nt<<<gemm_grid(BATCH, CD), 256>>>(q, Wq, nullptr, fq, BATCH, CD, QD, 1);
    add_kernel<<<(BATCH * CD + EW - 1) / EW, EW>>>(fv, fq, fvq, BATCH * CD);

    // hoisted GRU1 input GEMM over all timesteps: [B*T, 3CD]
    sgemm_nt<<<gemm_grid(BATCH * TT, 3 * CD), 256>>>(caption, w_ih1, b_ih1, gi1,
                                                     BATCH * TT, 3 * CD, CD, 0);

    // sequential recurrence
    for (int t = 0; t < TT; t++) {
        sgemm_nt<<<gemm_grid(BATCH, 3 * CD), 256>>>(h1, w_hh1, b_hh1, gh1,
                                                    BATCH, 3 * CD, CD, 0);
        gru1_att_kernel<<<(BATCH * CD + EW - 1) / EW, EW>>>(
            gi1, gh1, caption, fvq, cap_len, h1, att, alphas, t);

        sgemm_nt<<<gemm_grid(BATCH, 3 * HD), 256>>>(att, w_ih2, b_ih2, gi2,
                                                    BATCH, 3 * HD, CD, 0);
        sgemm_nt<<<gemm_grid(BATCH, 3 * HD), 256>>>(h2, w_hh2, b_hh2, gh2,
                                                    BATCH, 3 * HD, HD, 0);
        gru2_kernel<<<(BATCH * HD + EW - 1) / EW, EW>>>(
            gi2, gh2, cap_len, h2, h2a, t);
    }

    // hoisted output GEMM + masked leaky + time-max
    sgemm_nt<<<gemm_grid(BATCH * TT, HD), 256>>>(h2a, Wfc, nullptr, y,
                                                 BATCH * TT, HD, HD, 0);
    maxreduce_kernel<<<(BATCH * HD + EW - 1) / EW, EW>>>(y, cap_len, out);
}

// round 3
// speedup vs baseline: 2.5675x; 2.5675x over previous
#include <cuda_runtime.h>
#include <cstdint>
#include <math.h>

// Problem dims (fixed by the dataset)
#define BATCH 2048
#define TT    20
#define CD    512
#define HD    1024
#define VD    2048
#define QD    1024

// ---------------- scratch (static device globals; no runtime allocation) ----
__device__ float g_fv  [BATCH * CD];
__device__ float g_fq  [BATCH * CD];
__device__ float g_fvq [BATCH * CD];
__device__ float g_gi1 [BATCH * TT * 3 * CD];
__device__ float g_gh1 [BATCH * 3 * CD];
__device__ float g_att [BATCH * CD];
__device__ float g_gi2 [BATCH * 3 * HD];
__device__ float g_gh2 [BATCH * 3 * HD];
__device__ float g_h1  [BATCH * CD];
__device__ float g_h2  [BATCH * HD];
__device__ float g_h2a [BATCH * TT * HD];
__device__ float g_y   [BATCH * TT * HD];

// ---------------- helpers ----------------------------------------------------
__device__ __forceinline__ float sigmf(float x) { return 1.0f / (1.0f + expf(-x)); }
__device__ __forceinline__ float leakyf(float x) { return x > 0.0f ? x : 0.01f * x; }

__device__ __forceinline__ uint32_t tf32rna(float f) {
    uint32_t u;
    asm("cvt.rna.tf32.f32 %0, %1;" : "=r"(u) : "f"(f));
    return u;
}

// mma.sync m16n8k8 tf32, fp32 accumulate. Baseline PTX (sm_80+), no 'a' gating.
__device__ __forceinline__ void mma_tf32(
    float& c0, float& c1, float& c2, float& c3,
    uint32_t a0, uint32_t a1, uint32_t a2, uint32_t a3,
    uint32_t b0, uint32_t b1)
{
    asm volatile(
        "mma.sync.aligned.m16n8k8.row.col.f32.tf32.tf32.f32 "
        "{%0,%1,%2,%3}, {%4,%5,%6,%7}, {%8,%9}, {%0,%1,%2,%3};"
        : "+f"(c0), "+f"(c1), "+f"(c2), "+f"(c3)
        : "r"(a0), "r"(a1), "r"(a2), "r"(a3), "r"(b0), "r"(b1));
}

// ---------------- tf32 mma.sync GEMM: C[M,N] = A[M,K] @ B[N,K]^T (+bias,+leaky)
// Block tile 128x128, K-chunk 32, 256 threads (8 warps as 4m x 2n, warp 32x64).
// Requires M%128==0, N%128==0, K%32==0 (true for all calls here).
#define BK 32
#define LDS_STRIDE 36   // 32 + 4 pad: fragment loads conflict-free
#define TILE_WORDS (128 * LDS_STRIDE)

__global__ __launch_bounds__(256, 1) void tf32_gemm_nt(
    const float* __restrict__ A, const float* __restrict__ B,
    const float* __restrict__ bias, float* __restrict__ C,
    int M, int N, int K, int epi /*0=none,1=leaky*/)
{
    extern __shared__ uint32_t smem[];
    uint32_t* sA = smem;                      // [2][128][36]
    uint32_t* sB = smem + 2 * TILE_WORDS;     // [2][128][36]

    const int tid  = threadIdx.x;
    const int wid  = tid >> 5;
    const int lane = tid & 31;
    const int wm   = wid >> 1;    // 0..3 -> warp m offset wm*32
    const int wn   = wid & 1;     // 0..1 -> warp n offset wn*64
    const int g    = lane >> 2;   // groupID
    const int t    = lane & 3;    // threadID_in_group

    const int bm = blockIdx.y * 128;
    const int bn = blockIdx.x * 128;

    // loader geometry: 256 threads cover 32 rows x 8 vec4 per pass, 4 passes
    const int lrow = tid >> 3;    // 0..31
    const int lvec = tid & 7;     // 0..7

    const float* Ag = A + (size_t)(bm + lrow) * K + lvec * 4;
    const float* Bg = B + (size_t)(bn + lrow) * K + lvec * 4;

    float acc[2][8][4];
#pragma unroll
    for (int i = 0; i < 2; i++)
#pragma unroll
        for (int j = 0; j < 8; j++)
#pragma unroll
            for (int r = 0; r < 4; r++) acc[i][j][r] = 0.0f;

    const int NKC = K / BK;

    // preload chunk 0
    float4 av[4], bv[4];
#pragma unroll
    for (int p = 0; p < 4; p++) {
        av[p] = *(const float4*)(Ag + (size_t)p * 32 * K);
        bv[p] = *(const float4*)(Bg + (size_t)p * 32 * K);
    }

    for (int kc = 0; kc < NKC; kc++) {
        const int buf = kc & 1;
        uint32_t* a_st = sA + buf * TILE_WORDS + lrow * LDS_STRIDE + lvec * 4;
        uint32_t* b_st = sB + buf * TILE_WORDS + lrow * LDS_STRIDE + lvec * 4;
#pragma unroll
        for (int p = 0; p < 4; p++) {
            uint32_t* as = a_st + p * 32 * LDS_STRIDE;
            as[0] = tf32rna(av[p].x); as[1] = tf32rna(av[p].y);
            as[2] = tf32rna(av[p].z); as[3] = tf32rna(av[p].w);
            uint32_t* bs = b_st + p * 32 * LDS_STRIDE;
            bs[0] = tf32rna(bv[p].x); bs[1] = tf32rna(bv[p].y);
            bs[2] = tf32rna(bv[p].z); bs[3] = tf32rna(bv[p].w);
        }
        __syncthreads();

        // prefetch next chunk while computing
        if (kc + 1 < NKC) {
            const float* ap = Ag + (size_t)(kc + 1) * BK;
            const float* bp = Bg + (size_t)(kc + 1) * BK;
#pragma unroll
            for (int p = 0; p < 4; p++) {
                av[p] = *(const float4*)(ap + (size_t)p * 32 * K);
                bv[p] = *(const float4*)(bp + (size_t)p * 32 * K);
            }
        }

        const uint32_t* cA = sA + buf * TILE_WORDS;
        const uint32_t* cB = sB + buf * TILE_WORDS;
#pragma unroll
        for (int ks = 0; ks < 4; ks++) {
            const int k0 = ks * 8;
            uint32_t af[2][4];
#pragma unroll
            for (int mt = 0; mt < 2; mt++) {
                const int r0 = wm * 32 + mt * 16 + g;
                af[mt][0] = cA[(r0)     * LDS_STRIDE + k0 + t];
                af[mt][1] = cA[(r0 + 8) * LDS_STRIDE + k0 + t];
                af[mt][2] = cA[(r0)     * LDS_STRIDE + k0 + t + 4];
                af[mt][3] = cA[(r0 + 8) * LDS_STRIDE + k0 + t + 4];
            }
            uint32_t bf[8][2];
#pragma unroll
            for (int nt = 0; nt < 8; nt++) {
                const int n0 = wn * 64 + nt * 8 + g;
                bf[nt][0] = cB[n0 * LDS_STRIDE + k0 + t];
                bf[nt][1] = cB[n0 * LDS_STRIDE + k0 + t + 4];
            }
#pragma unroll
            for (int mt = 0; mt < 2; mt++)
#pragma unroll
                for (int nt = 0; nt < 8; nt++)
                    mma_tf32(acc[mt][nt][0], acc[mt][nt][1],
                             acc[mt][nt][2], acc[mt][nt][3],
                             af[mt][0], af[mt][1], af[mt][2], af[mt][3],
                             bf[nt][0], bf[nt][1]);
        }
        __syncthreads();
    }

    // epilogue: c0,c1 -> (row g, cols 2t,2t+1); c2,c3 -> (row g+8, same cols)
#pragma unroll
    for (int mt = 0; mt < 2; mt++) {
        const int r0 = bm + wm * 32 + mt * 16 + g;
#pragma unroll
        for (int nt = 0; nt < 8; nt++) {
            const int col = bn + wn * 64 + nt * 8 + 2 * t;
            float b0 = 0.0f, b1 = 0.0f;
            if (bias) { b0 = bias[col]; b1 = bias[col + 1]; }
            float v0 = acc[mt][nt][0] + b0;
            float v1 = acc[mt][nt][1] + b1;
            float v2 = acc[mt][nt][2] + b0;
            float v3 = acc[mt][nt][3] + b1;
            if (epi == 1) { v0 = leakyf(v0); v1 = leakyf(v1); v2 = leakyf(v2); v3 = leakyf(v3); }
            float2 lo = make_float2(v0, v1);
            float2 hi = make_float2(v2, v3);
            *(float2*)(C + (size_t)r0 * N + col)       = lo;
            *(float2*)(C + (size_t)(r0 + 8) * N + col) = hi;
        }
    }
}

#define SMEM_DYN_BYTES (4 * TILE_WORDS * 4)

// ---------------- elementwise kernels ----------------------------------------
__global__ void zero_kernel(float* p, int n) {
    int i = blockIdx.x * blockDim.x + threadIdx.x;
    if (i < n) p[i] = 0.0f;
}

__global__ void add_kernel(const float* __restrict__ a, const float* __restrict__ b,
                           float* __restrict__ c, int n) {
    int i = blockIdx.x * blockDim.x + threadIdx.x;
    if (i < n) c[i] = a[i] + b[i];
}

__global__ void gru1_att_kernel(
    const float* __restrict__ gi1, const float* __restrict__ gh1,
    const float* __restrict__ caption, const float* __restrict__ fvq,
    const int* __restrict__ cap_len,
    float* __restrict__ h1, float* __restrict__ att, float* __restrict__ alphas, int t)
{
    int idx = blockIdx.x * blockDim.x + threadIdx.x;
    if (idx >= BATCH * CD) return;
    int b = idx / CD, j = idx - b * CD;
    bool active = t < cap_len[b];

    const float* gi = gi1 + (size_t)(b * TT + t) * (3 * CD);
    const float* gh = gh1 + (size_t)b * (3 * CD);

    float hv = h1[idx];
    float r = sigmf(gi[j]          + gh[j]);
    float z = sigmf(gi[CD + j]     + gh[CD + j]);
    float n = tanhf(gi[2 * CD + j] + r * gh[2 * CD + j]);
    float hn = (1.0f - z) * n + z * hv;
    float h  = active ? hn : hv;
    h1[idx] = h;

    float x = caption[(size_t)(b * TT + t) * CD + j];
    float a = sigmf(h * fvq[idx]) * x;
    att[idx] = a;
    alphas[(size_t)(b * TT + t) * CD + j] = active ? a : 0.0f;
}

__global__ void gru2_kernel(
    const float* __restrict__ gi2, const float* __restrict__ gh2,
    const int* __restrict__ cap_len,
    float* __restrict__ h2, float* __restrict__ h2all, int t)
{
    int idx = blockIdx.x * blockDim.x + threadIdx.x;
    if (idx >= BATCH * HD) return;
    int b = idx / HD, j = idx - b * HD;
    bool active = t < cap_len[b];

    const float* gi = gi2 + (size_t)b * (3 * HD);
    const float* gh = gh2 + (size_t)b * (3 * HD);

    float hv = h2[idx];
    float r = sigmf(gi[j]          + gh[j]);
    float z = sigmf(gi[HD + j]     + gh[HD + j]);
    float n = tanhf(gi[2 * HD + j] + r * gh[2 * HD + j]);
    float hn = (1.0f - z) * n + z * hv;
    float h  = active ? hn : hv;
    h2[idx] = h;
    h2all[(size_t)(b * TT + t) * HD + j] = h;
}

__global__ void maxreduce_kernel(
    const float* __restrict__ Y, const int* __restrict__ cap_len, float* __restrict__ out)
{
    int idx = blockIdx.x * blockDim.x + threadIdx.x;
    if (idx >= BATCH * HD) return;
    int b = idx / HD, j = idx - b * HD;
    int len = cap_len[b];
    float m = -INFINITY;
#pragma unroll
    for (int t = 0; t < TT; t++) {
        float v = (t < len) ? leakyf(Y[(size_t)(b * TT + t) * HD + j]) : 0.0f;
        m = fmaxf(m, v);
    }
    out[idx] = m;
}

// ---------------- launch ------------------------------------------------------
static inline dim3 gemm_grid(int M, int N) { return dim3(N / 128, M / 128); }

extern "C" void kernel_launch(void* const* d_in, const int* in_sizes, int n_in,
                              void* d_out, int out_size)
{
    const float* v       = (const float*)d_in[0];
    const float* q       = (const float*)d_in[1];
    const float* caption = (const float*)d_in[2];
    const int*   cap_len = (const int*)  d_in[3];
    const float* w_ih1   = (const float*)d_in[4];
    const float* w_hh1   = (const float*)d_in[5];
    const float* b_ih1   = (const float*)d_in[6];
    const float* b_hh1   = (const float*)d_in[7];
    const float* w_ih2   = (const float*)d_in[8];
    const float* w_hh2   = (const float*)d_in[9];
    const float* b_ih2   = (const float*)d_in[10];
    const float* b_hh2   = (const float*)d_in[11];
    const float* Wv      = (const float*)d_in[12];
    const float* Wq      = (const float*)d_in[13];
    const float* Wfc     = (const float*)d_in[14];

    float* out    = (float*)d_out;
    float* alphas = (float*)d_out + (size_t)BATCH * HD;

    float *fv, *fq, *fvq, *gi1, *gh1, *att, *gi2, *gh2, *h1, *h2, *h2a, *y;
    cudaGetSymbolAddress((void**)&fv,  g_fv);
    cudaGetSymbolAddress((void**)&fq,  g_fq);
    cudaGetSymbolAddress((void**)&fvq, g_fvq);
    cudaGetSymbolAddress((void**)&gi1, g_gi1);
    cudaGetSymbolAddress((void**)&gh1, g_gh1);
    cudaGetSymbolAddress((void**)&att, g_att);
    cudaGetSymbolAddress((void**)&gi2, g_gi2);
    cudaGetSymbolAddress((void**)&gh2, g_gh2);
    cudaGetSymbolAddress((void**)&h1,  g_h1);
    cudaGetSymbolAddress((void**)&h2,  g_h2);
    cudaGetSymbolAddress((void**)&h2a, g_h2a);
    cudaGetSymbolAddress((void**)&y,   g_y);

    static bool attr_set = false;
    if (!attr_set) {
        cudaFuncSetAttribute(tf32_gemm_nt, cudaFuncAttributeMaxDynamicSharedMemorySize,
                             SMEM_DYN_BYTES);
        attr_set = true;
    }

    const int EW = 256;
    const int SD = SMEM_DYN_BYTES;

    zero_kernel<<<(BATCH * CD + EW - 1) / EW, EW>>>(h1, BATCH * CD);
    zero_kernel<<<(BATCH * HD + EW - 1) / EW, EW>>>(h2, BATCH * HD);

    // hoisted projections
    tf32_gemm_nt<<<gemm_grid(BATCH, CD), 256, SD>>>(v, Wv, nullptr, fv, BATCH, CD, VD, 1);
    tf32_gemm_nt<<<gemm_grid(BATCH, CD), 256, SD>>>(q, Wq, nullptr, fq, BATCH, CD, QD, 1);
    add_kernel<<<(BATCH * CD + EW - 1) / EW, EW>>>(fv, fq, fvq, BATCH * CD);

    // hoisted GRU1 input GEMM over all timesteps: [B*T, 3CD]
    tf32_gemm_nt<<<gemm_grid(BATCH * TT, 3 * CD), 256, SD>>>(caption, w_ih1, b_ih1, gi1,
                                                             BATCH * TT, 3 * CD, CD, 0);

    // sequential recurrence
    for (int t = 0; t < TT; t++) {
        tf32_gemm_nt<<<gemm_grid(BATCH, 3 * CD), 256, SD>>>(h1, w_hh1, b_hh1, gh1,
                                                            BATCH, 3 * CD, CD, 0);
        gru1_att_kernel<<<(BATCH * CD + EW - 1) / EW, EW>>>(
            gi1, gh1, caption, fvq, cap_len, h1, att, alphas, t);

        tf32_gemm_nt<<<gemm_grid(BATCH, 3 * HD), 256, SD>>>(att, w_ih2, b_ih2, gi2,
                                                            BATCH, 3 * HD, CD, 0);
        tf32_gemm_nt<<<gemm_grid(BATCH, 3 * HD), 256, SD>>>(h2, w_hh2, b_hh2, gh2,
                                                            BATCH, 3 * HD, HD, 0);
        gru2_kernel<<<(BATCH * HD + EW - 1) / EW, EW>>>(
            gi2, gh2, cap_len, h2, h2a, t);
    }

    // hoisted output GEMM + masked leaky + time-max
    tf32_gemm_nt<<<gemm_grid(BATCH * TT, HD), 256, SD>>>(h2a, Wfc, nullptr, y,
                                                         BATCH * TT, HD, HD, 0);
    maxreduce_kernel<<<(BATCH * HD + EW - 1) / EW, EW>>>(y, cap_len, out);
}

// round 4
// speedup vs baseline: 3.8152x; 1.4859x over previous
#include <cuda_runtime.h>
#include <cuda_fp16.h>
#include <cstdint>
#include <math.h>

// Problem dims (fixed by the dataset)
#define BATCH 2048
#define TT    20
#define CD    512
#define HD    1024
#define VD    2048
#define QD    1024

// ---------------- scratch (static device globals; no runtime allocation) ----
__device__ float g_fv  [BATCH * CD];
__device__ float g_fq  [BATCH * CD];
__device__ float g_fvq [BATCH * CD];
__device__ float g_gi1 [BATCH * TT * 3 * CD];
__device__ float g_gh1 [BATCH * 3 * CD];
__device__ float g_att [BATCH * CD];
__device__ float g_gi2 [BATCH * 3 * HD];
__device__ float g_gh2 [BATCH * 3 * HD];
__device__ float g_h1  [BATCH * CD];
__device__ float g_h2  [BATCH * HD];
__device__ float g_h2a [BATCH * TT * HD];
__device__ float g_y   [BATCH * TT * HD];

// ---------------- helpers ----------------------------------------------------
__device__ __forceinline__ float sigmf(float x) { return 1.0f / (1.0f + expf(-x)); }
__device__ __forceinline__ float leakyf(float x) { return x > 0.0f ? x : 0.01f * x; }

__device__ __forceinline__ uint32_t packh2(float x, float y) {
    __half2 h = __floats2half2_rn(x, y);
    return *(uint32_t*)&h;
}

// mma.sync m16n8k16 fp16 inputs, fp32 accumulate. Baseline PTX (sm_80+).
__device__ __forceinline__ void mma_f16(
    float& c0, float& c1, float& c2, float& c3,
    uint32_t a0, uint32_t a1, uint32_t a2, uint32_t a3,
    uint32_t b0, uint32_t b1)
{
    asm volatile(
        "mma.sync.aligned.m16n8k16.row.col.f32.f16.f16.f32 "
        "{%0,%1,%2,%3}, {%4,%5,%6,%7}, {%8,%9}, {%0,%1,%2,%3};"
        : "+f"(c0), "+f"(c1), "+f"(c2), "+f"(c3)
        : "r"(a0), "r"(a1), "r"(a2), "r"(a3), "r"(b0), "r"(b1));
}

// ---------------- fp16 mma.sync GEMM: C[M,N] = A[M,K] @ B[N,K]^T (+bias,+leaky)
// Block tile 128x128, K-chunk 32 (16 k-pairs/row), 256 threads
// (8 warps as 4m x 2n, warp tile 32x64). M%128==0, N%128==0, K%32==0.
#define BK 32
#define KP 16            // k-pairs per row per chunk (BK/2)
#define LDS_STRIDE 20    // 16 data + 4 pad words; fragment access conflict-free
#define TILE_WORDS (128 * LDS_STRIDE)

__global__ __launch_bounds__(256, 1) void h16_gemm_nt(
    const float* __restrict__ A, const float* __restrict__ B,
    const float* __restrict__ bias, float* __restrict__ C,
    int M, int N, int K, int epi /*0=none,1=leaky*/)
{
    __shared__ uint32_t smem[4 * TILE_WORDS];   // A0,A1,B0,B1 (40 KB)
    uint32_t* sA = smem;
    uint32_t* sB = smem + 2 * TILE_WORDS;

    const int tid  = threadIdx.x;
    const int wid  = tid >> 5;
    const int lane = tid & 31;
    const int wm   = wid >> 1;    // 0..3
    const int wn   = wid & 1;     // 0..1
    const int g    = lane >> 2;   // 0..7
    const int t    = lane & 3;    // 0..3

    const int bm = blockIdx.y * 128;
    const int bn = blockIdx.x * 128;

    // loader: 256 threads = 32 rows x 8 float4-vectors; 4 passes of 32 rows
    const int lrow = tid >> 3;    // 0..31
    const int lvec = tid & 7;     // 0..7

    const float* Ag = A + (size_t)(bm + lrow) * K + lvec * 4;
    const float* Bg = B + (size_t)(bn + lrow) * K + lvec * 4;

    float acc[2][8][4];
#pragma unroll
    for (int i = 0; i < 2; i++)
#pragma unroll
        for (int j = 0; j < 8; j++)
#pragma unroll
            for (int r = 0; r < 4; r++) acc[i][j][r] = 0.0f;

    const int NKC = K / BK;

    // preload chunk 0
    float4 av[4], bv[4];
#pragma unroll
    for (int p = 0; p < 4; p++) {
        av[p] = *(const float4*)(Ag + (size_t)p * 32 * K);
        bv[p] = *(const float4*)(Bg + (size_t)p * 32 * K);
    }

    for (int kc = 0; kc < NKC; kc++) {
        const int buf = kc & 1;
        uint32_t* a_st = sA + buf * TILE_WORDS + lrow * LDS_STRIDE + lvec * 2;
        uint32_t* b_st = sB + buf * TILE_WORDS + lrow * LDS_STRIDE + lvec * 2;
#pragma unroll
        for (int p = 0; p < 4; p++) {
            uint2 ua = make_uint2(packh2(av[p].x, av[p].y), packh2(av[p].z, av[p].w));
            uint2 ub = make_uint2(packh2(bv[p].x, bv[p].y), packh2(bv[p].z, bv[p].w));
            *(uint2*)(a_st + p * 32 * LDS_STRIDE) = ua;
            *(uint2*)(b_st + p * 32 * LDS_STRIDE) = ub;
        }
        __syncthreads();

        // prefetch next chunk while computing
        if (kc + 1 < NKC) {
            const float* ap = Ag + (size_t)(kc + 1) * BK;
            const float* bp = Bg + (size_t)(kc + 1) * BK;
#pragma unroll
            for (int p = 0; p < 4; p++) {
                av[p] = *(const float4*)(ap + (size_t)p * 32 * K);
                bv[p] = *(const float4*)(bp + (size_t)p * 32 * K);
            }
        }

        const uint32_t* cA = sA + buf * TILE_WORDS;
        const uint32_t* cB = sB + buf * TILE_WORDS;
#pragma unroll
        for (int ks = 0; ks < 2; ks++) {          // two k16 steps per chunk
            const int kp0 = ks * 8;
            uint32_t af[2][4];
#pragma unroll
            for (int mt = 0; mt < 2; mt++) {
                const int r0 = wm * 32 + mt * 16 + g;
                af[mt][0] = cA[(r0)     * LDS_STRIDE + kp0 + t];
                af[mt][1] = cA[(r0 + 8) * LDS_STRIDE + kp0 + t];
                af[mt][2] = cA[(r0)     * LDS_STRIDE + kp0 + t + 4];
                af[mt][3] = cA[(r0 + 8) * LDS_STRIDE + kp0 + t + 4];
            }
            uint32_t bf[8][2];
#pragma unroll
            for (int nt = 0; nt < 8; nt++) {
                const int n0 = wn * 64 + nt * 8 + g;
                bf[nt][0] = cB[n0 * LDS_STRIDE + kp0 + t];
                bf[nt][1] = cB[n0 * LDS_STRIDE + kp0 + t + 4];
            }
#pragma unroll
            for (int mt = 0; mt < 2; mt++)
#pragma unroll
                for (int nt = 0; nt < 8; nt++)
                    mma_f16(acc[mt][nt][0], acc[mt][nt][1],
                            acc[mt][nt][2], acc[mt][nt][3],
                            af[mt][0], af[mt][1], af[mt][2], af[mt][3],
                            bf[nt][0], bf[nt][1]);
        }
        __syncthreads();
    }

    // epilogue: c0,c1 -> (row g, cols 2t,2t+1); c2,c3 -> (row g+8, same cols)
#pragma unroll
    for (int mt = 0; mt < 2; mt++) {
        const int r0 = bm + wm * 32 + mt * 16 + g;
#pragma unroll
        for (int nt = 0; nt < 8; nt++) {
            const int col = bn + wn * 64 + nt * 8 + 2 * t;
            float b0 = 0.0f, b1 = 0.0f;
            if (bias) { b0 = bias[col]; b1 = bias[col + 1]; }
            float v0 = acc[mt][nt][0] + b0;
            float v1 = acc[mt][nt][1] + b1;
            float v2 = acc[mt][nt][2] + b0;
            float v3 = acc[mt][nt][3] + b1;
            if (epi == 1) { v0 = leakyf(v0); v1 = leakyf(v1); v2 = leakyf(v2); v3 = leakyf(v3); }
            *(float2*)(C + (size_t)r0 * N + col)       = make_float2(v0, v1);
            *(float2*)(C + (size_t)(r0 + 8) * N + col) = make_float2(v2, v3);
        }
    }
}

// ---------------- elementwise kernels ----------------------------------------
__global__ void zero_kernel(float* p, int n) {
    int i = blockIdx.x * blockDim.x + threadIdx.x;
    if (i < n) p[i] = 0.0f;
}

__global__ void add_kernel(const float* __restrict__ a, const float* __restrict__ b,
                           float* __restrict__ c, int n) {
    int i = blockIdx.x * blockDim.x + threadIdx.x;
    if (i < n) c[i] = a[i] + b[i];
}

__global__ void gru1_att_kernel(
    const float* __restrict__ gi1, const float* __restrict__ gh1,
    const float* __restrict__ caption, const float* __restrict__ fvq,
    const int* __restrict__ cap_len,
    float* __restrict__ h1, float* __restrict__ att, float* __restrict__ alphas, int t)
{
    int idx = blockIdx.x * blockDim.x + threadIdx.x;
    if (idx >= BATCH * CD) return;
    int b = idx / CD, j = idx - b * CD;
    bool active = t < cap_len[b];

    const float* gi = gi1 + (size_t)(b * TT + t) * (3 * CD);
    const float* gh = gh1 + (size_t)b * (3 * CD);

    float hv = h1[idx];
    float r = sigmf(gi[j]          + gh[j]);
    float z = sigmf(gi[CD + j]     + gh[CD + j]);
    float n = tanhf(gi[2 * CD + j] + r * gh[2 * CD + j]);
    float hn = (1.0f - z) * n + z * hv;
    float h  = active ? hn : hv;
    h1[idx] = h;

    float x = caption[(size_t)(b * TT + t) * CD + j];
    float a = sigmf(h * fvq[idx]) * x;
    att[idx] = a;
    alphas[(size_t)(b * TT + t) * CD + j] = active ? a : 0.0f;
}

__global__ void gru2_kernel(
    const float* __restrict__ gi2, const float* __restrict__ gh2,
    const int* __restrict__ cap_len,
    float* __restrict__ h2, float* __restrict__ h2all, int t)
{
    int idx = blockIdx.x * blockDim.x + threadIdx.x;
    if (idx >= BATCH * HD) return;
    int b = idx / HD, j = idx - b * HD;
    bool active = t < cap_len[b];

    const float* gi = gi2 + (size_t)b * (3 * HD);
    const float* gh = gh2 + (size_t)b * (3 * HD);

    float hv = h2[idx];
    float r = sigmf(gi[j]          + gh[j]);
    float z = sigmf(gi[HD + j]     + gh[HD + j]);
    float n = tanhf(gi[2 * HD + j] + r * gh[2 * HD + j]);
    float hn = (1.0f - z) * n + z * hv;
    float h  = active ? hn : hv;
    h2[idx] = h;
    h2all[(size_t)(b * TT + t) * HD + j] = h;
}

__global__ void maxreduce_kernel(
    const float* __restrict__ Y, const int* __restrict__ cap_len, float* __restrict__ out)
{
    int idx = blockIdx.x * blockDim.x + threadIdx.x;
    if (idx >= BATCH * HD) return;
    int b = idx / HD, j = idx - b * HD;
    int len = cap_len[b];
    float m = -INFINITY;
#pragma unroll
    for (int t = 0; t < TT; t++) {
        float v = (t < len) ? leakyf(Y[(size_t)(b * TT + t) * HD + j]) : 0.0f;
        m = fmaxf(m, v);
    }
    out[idx] = m;
}

// ---------------- launch ------------------------------------------------------
static inline dim3 gemm_grid(int M, int N) { return dim3(N / 128, M / 128); }

extern "C" void kernel_launch(void* const* d_in, const int* in_sizes, int n_in,
                              void* d_out, int out_size)
{
    const float* v       = (const float*)d_in[0];
    const float* q       = (const float*)d_in[1];
    const float* caption = (const float*)d_in[2];
    const int*   cap_len = (const int*)  d_in[3];
    const float* w_ih1   = (const float*)d_in[4];
    const float* w_hh1   = (const float*)d_in[5];
    const float* b_ih1   = (const float*)d_in[6];
    const float* b_hh1   = (const float*)d_in[7];
    const float* w_ih2   = (const float*)d_in[8];
    const float* w_hh2   = (const float*)d_in[9];
    const float* b_ih2   = (const float*)d_in[10];
    const float* b_hh2   = (const float*)d_in[11];
    const float* Wv      = (const float*)d_in[12];
    const float* Wq      = (const float*)d_in[13];
    const float* Wfc     = (const float*)d_in[14];

    float* out    = (float*)d_out;
    float* alphas = (float*)d_out + (size_t)BATCH * HD;

    float *fv, *fq, *fvq, *gi1, *gh1, *att, *gi2, *gh2, *h1, *h2, *h2a, *y;
    cudaGetSymbolAddress((void**)&fv,  g_fv);
    cudaGetSymbolAddress((void**)&fq,  g_fq);
    cudaGetSymbolAddress((void**)&fvq, g_fvq);
    cudaGetSymbolAddress((void**)&gi1, g_gi1);
    cudaGetSymbolAddress((void**)&gh1, g_gh1);
    cudaGetSymbolAddress((void**)&att, g_att);
    cudaGetSymbolAddress((void**)&gi2, g_gi2);
    cudaGetSymbolAddress((void**)&gh2, g_gh2);
    cudaGetSymbolAddress((void**)&h1,  g_h1);
    cudaGetSymbolAddress((void**)&h2,  g_h2);
    cudaGetSymbolAddress((void**)&h2a, g_h2a);
    cudaGetSymbolAddress((void**)&y,   g_y);

    const int EW = 256;

    zero_kernel<<<(BATCH * CD + EW - 1) / EW, EW>>>(h1, BATCH * CD);
    zero_kernel<<<(BATCH * HD + EW - 1) / EW, EW>>>(h2, BATCH * HD);

    // hoisted projections
    h16_gemm_nt<<<gemm_grid(BATCH, CD), 256>>>(v, Wv, nullptr, fv, BATCH, CD, VD, 1);
    h16_gemm_nt<<<gemm_grid(BATCH, CD), 256>>>(q, Wq, nullptr, fq, BATCH, CD, QD, 1);
    add_kernel<<<(BATCH * CD + EW - 1) / EW, EW>>>(fv, fq, fvq, BATCH * CD);

    // hoisted GRU1 input GEMM over all timesteps: [B*T, 3CD]
    h16_gemm_nt<<<gemm_grid(BATCH * TT, 3 * CD), 256>>>(caption, w_ih1, b_ih1, gi1,
                                                        BATCH * TT, 3 * CD, CD, 0);

    // sequential recurrence
    for (int t = 0; t < TT; t++) {
        h16_gemm_nt<<<gemm_grid(BATCH, 3 * CD), 256>>>(h1, w_hh1, b_hh1, gh1,
                                                       BATCH, 3 * CD, CD, 0);
        gru1_att_kernel<<<(BATCH * CD + EW - 1) / EW, EW>>>(
            gi1, gh1, caption, fvq, cap_len, h1, att, alphas, t);

        h16_gemm_nt<<<gemm_grid(BATCH, 3 * HD), 256>>>(att, w_ih2, b_ih2, gi2,
                                                       BATCH, 3 * HD, CD, 0);
        h16_gemm_nt<<<gemm_grid(BATCH, 3 * HD), 256>>>(h2, w_hh2, b_hh2, gh2,
                                                       BATCH, 3 * HD, HD, 0);
        gru2_kernel<<<(BATCH * HD + EW - 1) / EW, EW>>>(
            gi2, gh2, cap_len, h2, h2a, t);
    }

    // hoisted output GEMM + masked leaky + time-max
    h16_gemm_nt<<<gemm_grid(BATCH * TT, HD), 256>>>(h2a, Wfc, nullptr, y,
                                                    BATCH * TT, HD, HD, 0);
    maxreduce_kernel<<<(BATCH * HD + EW - 1) / EW, EW>>>(y, cap_len, out);
}

// round 5
// speedup vs baseline: 5.9370x; 1.5561x over previous
#include <cuda_runtime.h>
#include <cuda_fp16.h>
#include <cstdint>
#include <math.h>

// Problem dims (fixed by the dataset)
#define BATCH 2048
#define TT    20
#define CD    512
#define HD    1024
#define VD    2048
#define QD    1024

// ---------------- fp32 scratch ------------------------------------------------
__device__ float g_fv  [BATCH * CD];
__device__ float g_fq  [BATCH * CD];
__device__ float g_fvq [BATCH * CD];
__device__ float g_gi1 [BATCH * TT * 3 * CD];
__device__ float g_gh1 [BATCH * 3 * CD];
__device__ float g_gi2 [BATCH * 3 * HD];
__device__ float g_gh2 [BATCH * 3 * HD];
__device__ float g_h1  [BATCH * CD];
__device__ float g_h2  [BATCH * HD];
__device__ float g_y   [BATCH * TT * HD];

// ---------------- fp16 scratch (GEMM operands) --------------------------------
__device__ __half g_c16   [BATCH * TT * CD];
__device__ __half g_v16   [BATCH * VD];
__device__ __half g_q16   [BATCH * QD];
__device__ __half g_wih1h [3 * CD * CD];
__device__ __half g_whh1h [3 * CD * CD];
__device__ __half g_wih2h [3 * HD * CD];
__device__ __half g_whh2h [3 * HD * HD];
__device__ __half g_wvh   [CD * VD];
__device__ __half g_wqh   [CD * QD];
__device__ __half g_wfch  [HD * HD];
__device__ __half g_h1h   [BATCH * CD];
__device__ __half g_atth  [BATCH * CD];
__device__ __half g_h2h   [BATCH * HD];
__device__ __half g_h2ah  [BATCH * TT * HD];

// ---------------- helpers ------------------------------------------------------
__device__ __forceinline__ float sigmf(float x) { return 1.0f / (1.0f + expf(-x)); }
__device__ __forceinline__ float leakyf(float x) { return x > 0.0f ? x : 0.01f * x; }

__device__ __forceinline__ void mma_f16(
    float& c0, float& c1, float& c2, float& c3,
    uint32_t a0, uint32_t a1, uint32_t a2, uint32_t a3,
    uint32_t b0, uint32_t b1)
{
    asm volatile(
        "mma.sync.aligned.m16n8k16.row.col.f32.f16.f16.f32 "
        "{%0,%1,%2,%3}, {%4,%5,%6,%7}, {%8,%9}, {%0,%1,%2,%3};"
        : "+f"(c0), "+f"(c1), "+f"(c2), "+f"(c3)
        : "r"(a0), "r"(a1), "r"(a2), "r"(a3), "r"(b0), "r"(b1));
}

__device__ __forceinline__ void ldm_x4(uint32_t& r0, uint32_t& r1, uint32_t& r2, uint32_t& r3,
                                       uint32_t saddr)
{
    asm volatile("ldmatrix.sync.aligned.m8n8.x4.shared.b16 {%0,%1,%2,%3}, [%4];"
                 : "=r"(r0), "=r"(r1), "=r"(r2), "=r"(r3) : "r"(saddr));
}

__device__ __forceinline__ void cp16(uint32_t saddr, const void* gptr) {
    asm volatile("cp.async.cg.shared.global [%0], [%1], 16;" :: "r"(saddr), "l"(gptr));
}
__device__ __forceinline__ void cp_commit() {
    asm volatile("cp.async.commit_group;");
}
__device__ __forceinline__ void cp_wait1() {
    asm volatile("cp.async.wait_group 1;");
}

// ---------------- fp16 GEMM: C[M,N] = A[M,K]h @ B[N,K]h^T (+bias fp32,+leaky) --
// 128x128 tile, K-chunk 32, 256 threads (8 warps 4m x 2n, warp 32x64).
// 3-stage cp.async pipeline, ldmatrix.x4 fragments.
// M%128==0, N%128==0, K%32==0.
#define LDSH 40                       // halves per row in smem (32 data + 8 pad)
#define TILEB (128 * LDSH * 2)        // 10240 bytes per tile
#define STAGEB (2 * TILEB)            // A + B
#define SMEM_DYN_BYTES (3 * STAGEB)   // 61440

__global__ __launch_bounds__(256, 2) void h16_gemm_nt(
    const __half* __restrict__ A, const __half* __restrict__ B,
    const float* __restrict__ bias, float* __restrict__ C,
    int M, int N, int K, int epi /*0=none,1=leaky*/)
{
    extern __shared__ __align__(16) char smem[];

    const int tid  = threadIdx.x;
    const int wid  = tid >> 5;
    const int lane = tid & 31;
    const int wm   = wid >> 1;    // 0..3
    const int wn   = wid & 1;     // 0..1
    const int g    = lane >> 2;   // 0..7
    const int t    = lane & 3;    // 0..3

    const int bm = blockIdx.y * 128;
    const int bn = blockIdx.x * 128;

    const __half* Ag = A + (size_t)bm * K;
    const __half* Bg = B + (size_t)bn * K;

    const uint32_t sbase = (uint32_t)__cvta_generic_to_shared(smem);

    // cp.async loader geometry: 512 slots (128 rows x 4 vec16B) / 256 thr = 2 each
    const int r0s = tid >> 2, v0s = tid & 3;            // slot p=0
    const int r1s = (tid + 256) >> 2, v1s = tid & 3;    // slot p=1 (vec same: (tid+256)&3 == tid&3)

    // ldmatrix per-lane invariants
    const uint32_t a_off = (uint32_t)(((lane & 15) * LDSH + (lane >> 4) * 8) * 2);
    const int b_row = ((lane >> 4) << 3) + (lane & 7);
    const uint32_t b_koff = (uint32_t)((((lane >> 3) & 1) * 8) * 2);

    float acc[2][8][4];
#pragma unroll
    for (int i = 0; i < 2; i++)
#pragma unroll
        for (int j = 0; j < 8; j++)
#pragma unroll
            for (int r = 0; r < 4; r++) acc[i][j][r] = 0.0f;

    const int NKC = K >> 5;

    // issue a chunk's copies into stage buffer
    auto issue = [&](int kc) {
        const int st = kc % 3;
        const uint32_t sa = sbase + st * STAGEB;
        const uint32_t sb = sa + TILEB;
        const __half* ga0 = Ag + (size_t)r0s * K + kc * 32 + v0s * 8;
        const __half* gb0 = Bg + (size_t)r0s * K + kc * 32 + v0s * 8;
        const __half* ga1 = Ag + (size_t)r1s * K + kc * 32 + v1s * 8;
        const __half* gb1 = Bg + (size_t)r1s * K + kc * 32 + v1s * 8;
        const uint32_t o0 = (uint32_t)((r0s * LDSH + v0s * 8) * 2);
        const uint32_t o1 = (uint32_t)((r1s * LDSH + v1s * 8) * 2);
        cp16(sa + o0, ga0); cp16(sb + o0, gb0);
        cp16(sa + o1, ga1); cp16(sb + o1, gb1);
        cp_commit();
    };

    issue(0);
    issue(1);

    for (int kc = 0; kc < NKC; kc++) {
        cp_wait1();
        __syncthreads();

        const int st = kc % 3;
        const uint32_t cAb = sbase + st * STAGEB;
        const uint32_t cBb = cAb + TILEB;

#pragma unroll
        for (int ks = 0; ks < 2; ks++) {
            const uint32_t kso = (uint32_t)(ks * 16 * 2);
            uint32_t af[2][4];
#pragma unroll
            for (int mt = 0; mt < 2; mt++) {
                const uint32_t addr = cAb + (uint32_t)((wm * 32 + mt * 16) * LDSH * 2)
                                     + a_off + kso;
                ldm_x4(af[mt][0], af[mt][1], af[mt][2], af[mt][3], addr);
            }
            uint32_t bf[8][2];
#pragma unroll
            for (int p = 0; p < 4; p++) {
                const uint32_t addr = cBb
                    + (uint32_t)(((wn * 64 + p * 16 + b_row) * LDSH) * 2)
                    + kso + b_koff;
                ldm_x4(bf[2 * p][0], bf[2 * p][1], bf[2 * p + 1][0], bf[2 * p + 1][1], addr);
            }
#pragma unroll
            for (int mt = 0; mt < 2; mt++)
#pragma unroll
                for (int nt = 0; nt < 8; nt++)
                    mma_f16(acc[mt][nt][0], acc[mt][nt][1],
                            acc[mt][nt][2], acc[mt][nt][3],
                            af[mt][0], af[mt][1], af[mt][2], af[mt][3],
                            bf[nt][0], bf[nt][1]);
        }

        const int nxt = kc + 2;
        if (nxt < NKC) issue(nxt);
    }

    // epilogue: c0,c1 -> (row g, cols 2t,2t+1); c2,c3 -> (row g+8)
#pragma unroll
    for (int mt = 0; mt < 2; mt++) {
        const int r0 = bm + wm * 32 + mt * 16 + g;
#pragma unroll
        for (int nt = 0; nt < 8; nt++) {
            const int col = bn + wn * 64 + nt * 8 + 2 * t;
            float b0 = 0.0f, b1 = 0.0f;
            if (bias) { b0 = bias[col]; b1 = bias[col + 1]; }
            float v0 = acc[mt][nt][0] + b0;
            float v1 = acc[mt][nt][1] + b1;
            float v2 = acc[mt][nt][2] + b0;
            float v3 = acc[mt][nt][3] + b1;
            if (epi == 1) { v0 = leakyf(v0); v1 = leakyf(v1); v2 = leakyf(v2); v3 = leakyf(v3); }
            *(float2*)(C + (size_t)r0 * N + col)       = make_float2(v0, v1);
            *(float2*)(C + (size_t)(r0 + 8) * N + col) = make_float2(v2, v3);
        }
    }
}

// ---------------- conversion / elementwise kernels -----------------------------
__global__ void f2h_kernel(const float* __restrict__ src, __half* __restrict__ dst, int n) {
    int i = (blockIdx.x * blockDim.x + threadIdx.x) * 4;
    if (i < n) {
        float4 f = *(const float4*)(src + i);
        __half2 h0 = __floats2half2_rn(f.x, f.y);
        __half2 h1 = __floats2half2_rn(f.z, f.w);
        *(__half2*)(dst + i)     = h0;
        *(__half2*)(dst + i + 2) = h1;
    }
}

__global__ void zero_state_kernel(float* __restrict__ f, __half* __restrict__ h, int n) {
    int i = blockIdx.x * blockDim.x + threadIdx.x;
    if (i < n) { f[i] = 0.0f; h[i] = __float2half(0.0f); }
}

__global__ void add_kernel(const float* __restrict__ a, const float* __restrict__ b,
                           float* __restrict__ c, int n) {
    int i = blockIdx.x * blockDim.x + threadIdx.x;
    if (i < n) c[i] = a[i] + b[i];
}

// GRU1 gates + attention; writes fp32 state + fp16 mirrors + alphas
__global__ void gru1_att_kernel(
    const float* __restrict__ gi1, const float* __restrict__ gh1,
    const float* __restrict__ caption, const float* __restrict__ fvq,
    const int* __restrict__ cap_len,
    float* __restrict__ h1, __half* __restrict__ h1h,
    __half* __restrict__ atth, float* __restrict__ alphas, int t)
{
    int idx = blockIdx.x * blockDim.x + threadIdx.x;
    if (idx >= BATCH * CD) return;
    int b = idx / CD, j = idx - b * CD;
    bool active = t < cap_len[b];

    const float* gi = gi1 + (size_t)(b * TT + t) * (3 * CD);
    const float* gh = gh1 + (size_t)b * (3 * CD);

    float hv = h1[idx];
    float r = sigmf(gi[j]          + gh[j]);
    float z = sigmf(gi[CD + j]     + gh[CD + j]);
    float n = tanhf(gi[2 * CD + j] + r * gh[2 * CD + j]);
    float hn = (1.0f - z) * n + z * hv;
    float h  = active ? hn : hv;
    h1[idx]  = h;
    h1h[idx] = __float2half(h);

    float x = caption[(size_t)(b * TT + t) * CD + j];
    float a = sigmf(h * fvq[idx]) * x;
    atth[idx] = __float2half(a);
    alphas[(size_t)(b * TT + t) * CD + j] = active ? a : 0.0f;
}

// GRU2 gates; writes fp32 state + fp16 mirror + fp16 h2_all
__global__ void gru2_kernel(
    const float* __restrict__ gi2, const float* __restrict__ gh2,
    const int* __restrict__ cap_len,
    float* __restrict__ h2, __half* __restrict__ h2h,
    __half* __restrict__ h2ah, int t)
{
    int idx = blockIdx.x * blockDim.x + threadIdx.x;
    if (idx >= BATCH * HD) return;
    int b = idx / HD, j = idx - b * HD;
    bool active = t < cap_len[b];

    const float* gi = gi2 + (size_t)b * (3 * HD);
    const float* gh = gh2 + (size_t)b * (3 * HD);

    float hv = h2[idx];
    float r = sigmf(gi[j]          + gh[j]);
    float z = sigmf(gi[HD + j]     + gh[HD + j]);
    float n = tanhf(gi[2 * HD + j] + r * gh[2 * HD + j]);
    float hn = (1.0f - z) * n + z * hv;
    float h  = active ? hn : hv;
    h2[idx]  = h;
    __half hh = __float2half(h);
    h2h[idx] = hh;
    h2ah[(size_t)(b * TT + t) * HD + j] = hh;
}

__global__ void maxreduce_kernel(
    const float* __restrict__ Y, const int* __restrict__ cap_len, float* __restrict__ out)
{
    int idx = blockIdx.x * blockDim.x + threadIdx.x;
    if (idx >= BATCH * HD) return;
    int b = idx / HD, j = idx - b * HD;
    int len = cap_len[b];
    float m = -INFINITY;
#pragma unroll
    for (int t = 0; t < TT; t++) {
        float v = (t < len) ? leakyf(Y[(size_t)(b * TT + t) * HD + j]) : 0.0f;
        m = fmaxf(m, v);
    }
    out[idx] = m;
}

// ---------------- launch ---------------------------------------------------------
static inline dim3 gemm_grid(int M, int N) { return dim3(N / 128, M / 128); }

extern "C" void kernel_launch(void* const* d_in, const int* in_sizes, int n_in,
                              void* d_out, int out_size)
{
    const float* v       = (const float*)d_in[0];
    const float* q       = (const float*)d_in[1];
    const float* caption = (const float*)d_in[2];
    const int*   cap_len = (const int*)  d_in[3];
    const float* w_ih1   = (const float*)d_in[4];
    const float* w_hh1   = (const float*)d_in[5];
    const float* b_ih1   = (const float*)d_in[6];
    const float* b_hh1   = (const float*)d_in[7];
    const float* w_ih2   = (const float*)d_in[8];
    const float* w_hh2   = (const float*)d_in[9];
    const float* b_ih2   = (const float*)d_in[10];
    const float* b_hh2   = (const float*)d_in[11];
    const float* Wv      = (const float*)d_in[12];
    const float* Wq      = (const float*)d_in[13];
    const float* Wfc     = (const float*)d_in[14];

    float* out    = (float*)d_out;
    float* alphas = (float*)d_out + (size_t)BATCH * HD;

    float *fv, *fq, *fvq, *gi1, *gh1, *gi2, *gh2, *h1, *h2, *y;
    cudaGetSymbolAddress((void**)&fv,  g_fv);
    cudaGetSymbolAddress((void**)&fq,  g_fq);
    cudaGetSymbolAddress((void**)&fvq, g_fvq);
    cudaGetSymbolAddress((void**)&gi1, g_gi1);
    cudaGetSymbolAddress((void**)&gh1, g_gh1);
    cudaGetSymbolAddress((void**)&gi2, g_gi2);
    cudaGetSymbolAddress((void**)&gh2, g_gh2);
    cudaGetSymbolAddress((void**)&h1,  g_h1);
    cudaGetSymbolAddress((void**)&h2,  g_h2);
    cudaGetSymbolAddress((void**)&y,   g_y);

    __half *c16, *v16, *q16, *wih1h, *whh1h, *wih2h, *whh2h, *wvh, *wqh, *wfch;
    __half *h1h, *atth, *h2h, *h2ah;
    cudaGetSymbolAddress((void**)&c16,   g_c16);
    cudaGetSymbolAddress((void**)&v16,   g_v16);
    cudaGetSymbolAddress((void**)&q16,   g_q16);
    cudaGetSymbolAddress((void**)&wih1h, g_wih1h);
    cudaGetSymbolAddress((void**)&whh1h, g_whh1h);
    cudaGetSymbolAddress((void**)&wih2h, g_wih2h);
    cudaGetSymbolAddress((void**)&whh2h, g_whh2h);
    cudaGetSymbolAddress((void**)&wvh,   g_wvh);
    cudaGetSymbolAddress((void**)&wqh,   g_wqh);
    cudaGetSymbolAddress((void**)&wfch,  g_wfch);
    cudaGetSymbolAddress((void**)&h1h,   g_h1h);
    cudaGetSymbolAddress((void**)&atth,  g_atth);
    cudaGetSymbolAddress((void**)&h2h,   g_h2h);
    cudaGetSymbolAddress((void**)&h2ah,  g_h2ah);

    cudaFuncSetAttribute(h16_gemm_nt, cudaFuncAttributeMaxDynamicSharedMemorySize,
                         SMEM_DYN_BYTES);

    const int EW = 256;
    const int SD = SMEM_DYN_BYTES;
    auto cvt = [&](const float* s, __half* d, int n) {
        f2h_kernel<<<(n / 4 + EW - 1) / EW, EW>>>(s, d, n);
    };

    // one-time conversions to fp16
    cvt(caption, c16,   BATCH * TT * CD);
    cvt(v,       v16,   BATCH * VD);
    cvt(q,       q16,   BATCH * QD);
    cvt(w_ih1,   wih1h, 3 * CD * CD);
    cvt(w_hh1,   whh1h, 3 * CD * CD);
    cvt(w_ih2,   wih2h, 3 * HD * CD);
    cvt(w_hh2,   whh2h, 3 * HD * HD);
    cvt(Wv,      wvh,   CD * VD);
    cvt(Wq,      wqh,   CD * QD);
    cvt(Wfc,     wfch,  HD * HD);

    // init recurrent states (fp32 + fp16 mirror)
    zero_state_kernel<<<(BATCH * CD + EW - 1) / EW, EW>>>(h1, h1h, BATCH * CD);
    zero_state_kernel<<<(BATCH * HD + EW - 1) / EW, EW>>>(h2, h2h, BATCH * HD);

    // hoisted projections
    h16_gemm_nt<<<gemm_grid(BATCH, CD), 256, SD>>>(v16, wvh, nullptr, fv, BATCH, CD, VD, 1);
    h16_gemm_nt<<<gemm_grid(BATCH, CD), 256, SD>>>(q16, wqh, nullptr, fq, BATCH, CD, QD, 1);
    add_kernel<<<(BATCH * CD + EW - 1) / EW, EW>>>(fv, fq, fvq, BATCH * CD);

    // hoisted GRU1 input GEMM over all timesteps
    h16_gemm_nt<<<gemm_grid(BATCH * TT, 3 * CD), 256, SD>>>(c16, wih1h, b_ih1, gi1,
                                                            BATCH * TT, 3 * CD, CD, 0);

    // sequential recurrence
    for (int t = 0; t < TT; t++) {
        h16_gemm_nt<<<gemm_grid(BATCH, 3 * CD), 256, SD>>>(h1h, whh1h, b_hh1, gh1,
                                                           BATCH, 3 * CD, CD, 0);
        gru1_att_kernel<<<(BATCH * CD + EW - 1) / EW, EW>>>(
            gi1, gh1, caption, fvq, cap_len, h1, h1h, atth, alphas, t);

        h16_gemm_nt<<<gemm_grid(BATCH, 3 * HD), 256, SD>>>(atth, wih2h, b_ih2, gi2,
                                                           BATCH, 3 * HD, CD, 0);
        h16_gemm_nt<<<gemm_grid(BATCH, 3 * HD), 256, SD>>>(h2h, whh2h, b_hh2, gh2,
                                                           BATCH, 3 * HD, HD, 0);
        gru2_kernel<<<(BATCH * HD + EW - 1) / EW, EW>>>(
            gi2, gh2, cap_len, h2, h2h, h2ah, t);
    }

    // hoisted output GEMM + masked leaky + time-max
    h16_gemm_nt<<<gemm_grid(BATCH * TT, HD), 256, SD>>>(h2ah, wfch, nullptr, y,
                                                        BATCH * TT, HD, HD, 0);
    maxreduce_kernel<<<(BATCH * HD + EW - 1) / EW, EW>>>(y, cap_len, out);
}